// round 15
// baseline (speedup 1.0000x reference)
#include <cuda_runtime.h>
#include <cuda_bf16.h>
#include <cstdint>
#include <math.h>

#define Bb   4
#define Ss   1024
#define Dd   1024
#define Hh   16
#define DKk  64
#define NROWS (Bb * Ss)       // 4096

// ---------------- scratch (device globals; allocation-free rule) -----------
__device__ __nv_bfloat16 g_Ah[3 * NROWS * Dd];  // act hi (z slots: q,k,v / AO in 0)
__device__ __nv_bfloat16 g_Al[3 * NROWS * Dd];
__device__ __nv_bfloat16 g_Wh[4 * Dd * Dd];     // W^T hi (q,k,v,o)
__device__ __nv_bfloat16 g_Wl[4 * Dd * Dd];
__device__ __nv_bfloat16 g_Qh[NROWS * Dd];      // row-major [B*S, D] (head at h*64)
__device__ __nv_bfloat16 g_Ql[NROWS * Dd];
__device__ __nv_bfloat16 g_Kh[NROWS * Dd];
__device__ __nv_bfloat16 g_Kl[NROWS * Dd];
__device__ __nv_bfloat16 g_Vh[NROWS * Dd];
__device__ __nv_bfloat16 g_Vl[NROWS * Dd];
__device__ uint32_t g_maskbits[(size_t)Bb * Hh * Ss * (Ss / 32)];   // 8 MB
__device__ int g_mask_is_byte;

// ---------------- PTX helpers ----------------------------------------------
__device__ __forceinline__ uint32_t smem_u32(const void* p) {
    uint32_t a;
    asm("{ .reg .u64 t; cvta.to.shared.u64 t, %1; cvt.u32.u64 %0, t; }"
        : "=r"(a) : "l"(p));
    return a;
}
__device__ __forceinline__ void ldsm4(uint32_t* r, uint32_t addr) {
    asm volatile("ldmatrix.sync.aligned.m8n8.x4.shared.b16 {%0,%1,%2,%3}, [%4];"
                 : "=r"(r[0]), "=r"(r[1]), "=r"(r[2]), "=r"(r[3]) : "r"(addr));
}
__device__ __forceinline__ void ldsm4t(uint32_t* r, uint32_t addr) {
    asm volatile("ldmatrix.sync.aligned.m8n8.x4.trans.shared.b16 {%0,%1,%2,%3}, [%4];"
                 : "=r"(r[0]), "=r"(r[1]), "=r"(r[2]), "=r"(r[3]) : "r"(addr));
}
__device__ __forceinline__ void mma_bf16(float* c, const uint32_t* a, const uint32_t* b) {
    asm volatile("mma.sync.aligned.m16n8k16.row.col.f32.bf16.bf16.f32 "
                 "{%0,%1,%2,%3}, {%4,%5,%6,%7}, {%8,%9}, {%0,%1,%2,%3};"
                 : "+f"(c[0]), "+f"(c[1]), "+f"(c[2]), "+f"(c[3])
                 : "r"(a[0]), "r"(a[1]), "r"(a[2]), "r"(a[3]), "r"(b[0]), "r"(b[1]));
}
#define CP_ASYNC16(dst, src) \
    asm volatile("cp.async.cg.shared.global [%0], [%1], 16;" :: "r"(dst), "l"(src))
#define CP_COMMIT() asm volatile("cp.async.commit_group;" ::: "memory")
#define CP_WAIT2()  asm volatile("cp.async.wait_group 2;" ::: "memory")
#define CP_WAIT1()  asm volatile("cp.async.wait_group 1;" ::: "memory")
#define CP_WAIT0()  asm volatile("cp.async.wait_group 0;" ::: "memory")

// fast e^x. exp2 bit-trick + deg-5 poly (~1e-7 rel).
__device__ __forceinline__ float fast_exp(float x) {
    float t = x * 1.4426950408889634f;
    t = fmaxf(t, -126.0f);
    float fi = floorf(t);
    float f = t - fi;
    float p = 1.33336498402e-3f;
    p = fmaf(p, f, 9.81094791730e-3f);
    p = fmaf(p, f, 5.54906055839e-2f);
    p = fmaf(p, f, 2.40231509939e-1f);
    p = fmaf(p, f, 6.93146873954e-1f);
    p = fmaf(p, f, 1.0f);
    return __int_as_float(__float_as_int(p) + (((int)fi) << 23));
}

// ---------------------------------------------------------------------------
__global__ void detect_mask_kernel(const unsigned char* __restrict__ m)
{
    __shared__ int any;
    if (threadIdx.x == 0) any = 0;
    __syncthreads();
    int found = 0;
    for (int i = threadIdx.x; i < 4096; i += 256)
        if ((i & 3) != 0 && m[i] != 0) found = 1;
    if (found) atomicOr(&any, 1);
    __syncthreads();
    if (threadIdx.x == 0) g_mask_is_byte = any;
}

// pack mask -> bits. One warp per row of 1024.
__global__ __launch_bounds__(256)
void pack_mask_kernel(const void* __restrict__ mask_raw)
{
    const int row  = blockIdx.x * 8 + (threadIdx.x >> 5);
    const int lane = threadIdx.x & 31;
    uint32_t myw = 0;
    if (g_mask_is_byte) {
        const unsigned char* m = (const unsigned char*)mask_raw + (size_t)row * Ss;
#pragma unroll 4
        for (int it = 0; it < 32; it++) {
            uint32_t w = __ballot_sync(0xffffffffu, m[it * 32 + lane] != 0);
            if (it == lane) myw = w;
        }
    } else {
        const int* m = (const int*)mask_raw + (size_t)row * Ss;
#pragma unroll 4
        for (int it = 0; it < 32; it++) {
            uint32_t w = __ballot_sync(0xffffffffu, m[it * 32 + lane] != 0);
            if (it == lane) myw = w;
        }
    }
    g_maskbits[(size_t)row * 32 + lane] = myw;
}

// ---------------------------------------------------------------------------
// merged act conversion: z = 0,1,2 selects query/key/value
__global__ __launch_bounds__(256)
void conv_act_kernel(const float* __restrict__ A0, const float* __restrict__ A1,
                     const float* __restrict__ A2,
                     __nv_bfloat16* __restrict__ hiB, __nv_bfloat16* __restrict__ loB)
{
    const int z = blockIdx.y;
    const float* A = (z == 0) ? A0 : (z == 1) ? A1 : A2;
    __nv_bfloat16* hi = hiB + (size_t)z * NROWS * Dd;
    __nv_bfloat16* lo = loB + (size_t)z * NROWS * Dd;
    int i = blockIdx.x * 256 + threadIdx.x;
    float4 v = ((const float4*)A)[i];
    __nv_bfloat16 h0 = __float2bfloat16(v.x);
    __nv_bfloat16 h1 = __float2bfloat16(v.y);
    __nv_bfloat16 h2 = __float2bfloat16(v.z);
    __nv_bfloat16 h3 = __float2bfloat16(v.w);
    __nv_bfloat162 hA; hA.x = h0; hA.y = h1;
    __nv_bfloat162 hB; hB.x = h2; hB.y = h3;
    __nv_bfloat162 lA, lB;
    lA.x = __float2bfloat16(v.x - __bfloat162float(h0));
    lA.y = __float2bfloat16(v.y - __bfloat162float(h1));
    lB.x = __float2bfloat16(v.z - __bfloat162float(h2));
    lB.y = __float2bfloat16(v.w - __bfloat162float(h3));
    ((__nv_bfloat162*)hi)[i * 2 + 0] = hA;
    ((__nv_bfloat162*)hi)[i * 2 + 1] = hB;
    ((__nv_bfloat162*)lo)[i * 2 + 0] = lA;
    ((__nv_bfloat162*)lo)[i * 2 + 1] = lB;
}

// merged weight transpose+split: z = 0..3 selects Wq/Wk/Wv/Wo
__global__ __launch_bounds__(256)
void conv_wT_kernel(const float* __restrict__ W0, const float* __restrict__ W1,
                    const float* __restrict__ W2, const float* __restrict__ W3,
                    __nv_bfloat16* __restrict__ WhB, __nv_bfloat16* __restrict__ WlB)
{
    __shared__ float t[32][33];
    const int z = blockIdx.z;
    const float* W = (z == 0) ? W0 : (z == 1) ? W1 : (z == 2) ? W2 : W3;
    __nv_bfloat16* WhT = WhB + (size_t)z * Dd * Dd;
    __nv_bfloat16* WlT = WlB + (size_t)z * Dd * Dd;
    const int n0 = blockIdx.x * 32, k0 = blockIdx.y * 32;
    const int tx = threadIdx.x & 31, ty = threadIdx.x >> 5;
    for (int r = ty; r < 32; r += 8)
        t[r][tx] = W[(size_t)(k0 + r) * Dd + n0 + tx];
    __syncthreads();
    for (int r = ty; r < 32; r += 8) {
        float x = t[tx][r];
        __nv_bfloat16 h = __float2bfloat16(x);
        __nv_bfloat16 l = __float2bfloat16(x - __bfloat162float(h));
        WhT[(size_t)(n0 + r) * Dd + k0 + tx] = h;
        WlT[(size_t)(n0 + r) * Dd + k0 + tx] = l;
    }
}

// ---------------------------------------------------------------------------
// GEMM tile compute body (shared), plus 2-stage and 3-stage mainloops
// ---------------------------------------------------------------------------
#define KCH   32
#define NCHNK (Dd / KCH)
#define RSTB  80
#define TILEB (128 * RSTB)
#define STAGEB (4 * TILEB)
#define GEMM_SMEM2 (2 * STAGEB)
#define GEMM_SMEM3 (3 * STAGEB)

#define GEMM_LOADSTAGE_DEF(Ah, Al, Bh, Bl)                                     \
    auto load_stage = [&](int stg, int kc) {                                   \
        const uint32_t base = sb + stg * STAGEB;                               \
        _Pragma("unroll")                                                      \
        for (int e = 0; e < 2; e++) {                                          \
            const int row = r0 + e * 64;                                       \
            const uint32_t so = (uint32_t)row * RSTB + sg * 16;                \
            const size_t gaoff = (size_t)(m0 + row) * Dd + kc + sg * 8;        \
            const size_t gboff = (size_t)(n0 + row) * Dd + kc + sg * 8;        \
            CP_ASYNC16(base + 0 * TILEB + so, (const char*)(Ah + gaoff));      \
            CP_ASYNC16(base + 1 * TILEB + so, (const char*)(Al + gaoff));      \
            CP_ASYNC16(base + 2 * TILEB + so, (const char*)(Bh + gboff));      \
            CP_ASYNC16(base + 3 * TILEB + so, (const char*)(Bl + gboff));      \
        }                                                                      \
    };

#define GEMM_COMPUTE_STAGE(stg)                                                \
    {                                                                          \
        const uint32_t bA = sb + (stg) * STAGEB;                               \
        _Pragma("unroll")                                                      \
        for (int ks = 0; ks < 2; ks++) {                                       \
            const uint32_t koff = ks * 32 + (lane >> 4) * 16;                  \
            uint32_t ahf[2][4], alf[2][4], bhf[4][4], blf[4][4];               \
            _Pragma("unroll")                                                  \
            for (int mt = 0; mt < 2; mt++) {                                   \
                const uint32_t ro = (uint32_t)(wm * 32 + mt * 16 + (lane & 15)) * RSTB + koff; \
                ldsm4(ahf[mt], bA + 0 * TILEB + ro);                           \
                ldsm4(alf[mt], bA + 1 * TILEB + ro);                           \
            }                                                                  \
            _Pragma("unroll")                                                  \
            for (int np = 0; np < 4; np++) {                                   \
                const uint32_t ro = (uint32_t)(wn * 64 + np * 16 + (lane & 15)) * RSTB + koff; \
                ldsm4(bhf[np], bA + 2 * TILEB + ro);                           \
                ldsm4(blf[np], bA + 3 * TILEB + ro);                           \
            }                                                                  \
            _Pragma("unroll")                                                  \
            for (int mt = 0; mt < 2; mt++)                                     \
                _Pragma("unroll")                                              \
                for (int nt = 0; nt < 8; nt++) {                               \
                    uint32_t bh2[2] = { bhf[nt >> 1][nt & 1], bhf[nt >> 1][2 + (nt & 1)] }; \
                    uint32_t bl2[2] = { blf[nt >> 1][nt & 1], blf[nt >> 1][2 + (nt & 1)] }; \
                    mma_bf16(acc[mt][nt], ahf[mt], bh2);                       \
                    mma_bf16(acc[mt][nt], ahf[mt], bl2);                       \
                    mma_bf16(acc[mt][nt], alf[mt], bh2);                       \
                }                                                              \
        }                                                                      \
    }

#define GEMM_ACC_INIT                                                          \
    float acc[2][8][4];                                                        \
    _Pragma("unroll")                                                          \
    for (int mt = 0; mt < 2; mt++)                                             \
        _Pragma("unroll")                                                      \
        for (int nt = 0; nt < 8; nt++)                                         \
            _Pragma("unroll")                                                  \
            for (int j = 0; j < 4; j++) acc[mt][nt][j] = 0.f;

// merged QKV projection GEMM: 3-stage cp.async pipeline
__global__ __launch_bounds__(256)
void gemm_qkv_kernel(const __nv_bfloat16* __restrict__ AhB, const __nv_bfloat16* __restrict__ AlB,
                     const __nv_bfloat16* __restrict__ WhB, const __nv_bfloat16* __restrict__ WlB,
                     const float* __restrict__ b0, const float* __restrict__ b1,
                     const float* __restrict__ b2,
                     __nv_bfloat16* __restrict__ Qh, __nv_bfloat16* __restrict__ Ql,
                     __nv_bfloat16* __restrict__ Kh, __nv_bfloat16* __restrict__ Kl,
                     __nv_bfloat16* __restrict__ Vh, __nv_bfloat16* __restrict__ Vl)
{
    extern __shared__ char smem[];
    const uint32_t sb = smem_u32(smem);
    const int tid  = threadIdx.x;
    const int lane = tid & 31, wid = tid >> 5;
    const int wm = wid & 3, wn = wid >> 2;
    const int m0 = blockIdx.y * 128;
    const int n0 = blockIdx.x * 128;
    const int r0 = tid >> 2, sg = tid & 3;
    const int z  = blockIdx.z;

    const __nv_bfloat16* Ah = AhB + (size_t)z * NROWS * Dd;
    const __nv_bfloat16* Al = AlB + (size_t)z * NROWS * Dd;
    const __nv_bfloat16* Bh = WhB + (size_t)z * Dd * Dd;
    const __nv_bfloat16* Bl = WlB + (size_t)z * Dd * Dd;
    const float* bias = (z == 0) ? b0 : (z == 1) ? b1 : b2;
    __nv_bfloat16* Ch = (z == 0) ? Qh : (z == 1) ? Kh : Vh;
    __nv_bfloat16* Cl = (z == 0) ? Ql : (z == 1) ? Kl : Vl;

    GEMM_ACC_INIT
    GEMM_LOADSTAGE_DEF(Ah, Al, Bh, Bl)

    load_stage(0, 0);
    CP_COMMIT();
    load_stage(1, KCH);
    CP_COMMIT();

    int stg = 0;
    for (int ch = 0; ch < NCHNK; ch++) {
        if (ch + 2 < NCHNK) {
            load_stage((stg + 2) % 3, (ch + 2) * KCH);
            CP_COMMIT();
            CP_WAIT2();
        } else if (ch + 1 < NCHNK) {
            CP_WAIT1();
        } else {
            CP_WAIT0();
        }
        __syncthreads();
        GEMM_COMPUTE_STAGE(stg)
        __syncthreads();
        stg = (stg + 1) % 3;
    }

#pragma unroll
    for (int mt = 0; mt < 2; mt++) {
        const int r = m0 + wm * 32 + mt * 16 + (lane >> 2);
#pragma unroll
        for (int nt = 0; nt < 8; nt++) {
            const int c = n0 + wn * 64 + nt * 8 + 2 * (lane & 3);
            const float bb0 = bias[c], bb1 = bias[c + 1];
#pragma unroll
            for (int hf = 0; hf < 2; hf++) {
                const int rr = r + hf * 8;
                float v0 = acc[mt][nt][hf * 2 + 0] + bb0;
                float v1 = acc[mt][nt][hf * 2 + 1] + bb1;
                __nv_bfloat16 h0 = __float2bfloat16(v0);
                __nv_bfloat16 h1 = __float2bfloat16(v1);
                __nv_bfloat162 hi2; hi2.x = h0; hi2.y = h1;
                __nv_bfloat162 lo2;
                lo2.x = __float2bfloat16(v0 - __bfloat162float(h0));
                lo2.y = __float2bfloat16(v1 - __bfloat162float(h1));
                const size_t idx = (size_t)rr * Dd + c;
                *(__nv_bfloat162*)(Ch + idx) = hi2;
                *(__nv_bfloat162*)(Cl + idx) = lo2;
            }
        }
    }
}

// final output GEMM: 2-stage pipeline, fp32 epilogue, 2 CTAs/SM
__global__ __launch_bounds__(256, 2)
void gemm_out_kernel(const __nv_bfloat16* __restrict__ Ah, const __nv_bfloat16* __restrict__ Al,
                     const __nv_bfloat16* __restrict__ Bh, const __nv_bfloat16* __restrict__ Bl,
                     const float* __restrict__ bias, float* __restrict__ Cf)
{
    extern __shared__ char smem[];
    const uint32_t sb = smem_u32(smem);
    const int tid  = threadIdx.x;
    const int lane = tid & 31, wid = tid >> 5;
    const int wm = wid & 3, wn = wid >> 2;
    const int m0 = blockIdx.y * 128;
    const int n0 = blockIdx.x * 128;
    const int r0 = tid >> 2, sg = tid & 3;

    GEMM_ACC_INIT
    GEMM_LOADSTAGE_DEF(Ah, Al, Bh, Bl)

    load_stage(0, 0);
    CP_COMMIT();

    for (int ch = 0; ch < NCHNK; ch++) {
        if (ch + 1 < NCHNK) {
            load_stage((ch + 1) & 1, (ch + 1) * KCH);
            CP_COMMIT();
            CP_WAIT1();
        } else {
            CP_WAIT0();
        }
        __syncthreads();
        GEMM_COMPUTE_STAGE(ch & 1)
        __syncthreads();
    }

#pragma unroll
    for (int mt = 0; mt < 2; mt++) {
        const int r = m0 + wm * 32 + mt * 16 + (lane >> 2);
#pragma unroll
        for (int nt = 0; nt < 8; nt++) {
            const int c = n0 + wn * 64 + nt * 8 + 2 * (lane & 3);
            const float bb0 = bias[c], bb1 = bias[c + 1];
            float2 v0 = make_float2(acc[mt][nt][0] + bb0, acc[mt][nt][1] + bb1);
            float2 v1 = make_float2(acc[mt][nt][2] + bb0, acc[mt][nt][3] + bb1);
            *(float2*)&Cf[(size_t)r * Dd + c]       = v0;
            *(float2*)&Cf[(size_t)(r + 8) * Dd + c] = v1;
        }
    }
}

// ---------------------------------------------------------------------------
// Attention v3 (R14): fused mask+exp in QK^T epilogue; E bf16 hi/lo;
// row sums in registers; P2 normalize+stream; P3 scales AO by inv.
// ---------------------------------------------------------------------------
#define ESTRB  2096
#define OFF_EH 0
#define OFF_EL 67072
#define OFF_QH 134144
#define OFF_QL 138752
#define OFF_KH 143360
#define OFF_KL 152576
#define OFF_MB 161792
#define OFF_SUM 165888
#define OFF_INV 166400
#define ATTN_SMEM 166528

__global__ __launch_bounds__(256)
void attn_mma_kernel(float* __restrict__ attnw)
{
    extern __shared__ char sm[];
    const uint32_t sb = smem_u32(sm);

    const int blk = blockIdx.x;
    const int qt  = blk & 31;
    const int bh  = blk >> 5;
    const int q0  = qt * 32;
    const int tid = threadIdx.x;
    const int lane = tid & 31, wid = tid >> 5;
    const int wm = wid & 1;
    const int wn = wid >> 1;
    const int b  = bh >> 4, h = bh & 15;

    const __nv_bfloat16* QhB = g_Qh + ((size_t)b * Ss + q0) * Dd + h * DKk;
    const __nv_bfloat16* QlB = g_Ql + ((size_t)b * Ss + q0) * Dd + h * DKk;
    const __nv_bfloat16* KhB = g_Kh + (size_t)b * Ss * Dd + h * DKk;
    const __nv_bfloat16* KlB = g_Kl + (size_t)b * Ss * Dd + h * DKk;
    const __nv_bfloat16* VhB = g_Vh + (size_t)b * Ss * Dd + h * DKk;
    const __nv_bfloat16* VlB = g_Vl + (size_t)b * Ss * Dd + h * DKk;

    {
        int r = tid >> 3, sg = tid & 7;
        *(uint4*)(sm + OFF_QH + r * 144 + sg * 16) = ((const uint4*)(QhB + (size_t)r * Dd))[sg];
        *(uint4*)(sm + OFF_QL + r * 144 + sg * 16) = ((const uint4*)(QlB + (size_t)r * Dd))[sg];
        const uint4* msrc = (const uint4*)(g_maskbits + ((size_t)bh * Ss + q0 + r) * 32) + sg;
        *(uint4*)(sm + OFF_MB + r * 128 + sg * 16) = *msrc;
    }

    const int pr = tid >> 3, psg = tid & 7;
    uint4 rh[2], rl[2];
#define LDKV(Hb, Lb, c) do {                                                      \
    _Pragma("unroll")                                                             \
    for (int e = 0; e < 2; e++) {                                                 \
        int rr2 = pr + e * 32;                                                    \
        rh[e] = ((const uint4*)((Hb) + (size_t)((c) * 64 + rr2) * Dd))[psg];      \
        rl[e] = ((const uint4*)((Lb) + (size_t)((c) * 64 + rr2) * Dd))[psg];      \
    } } while (0)
#define STKV() do {                                                              \
    _Pragma("unroll")                                                             \
    for (int e = 0; e < 2; e++) {                                                 \
        int rr2 = pr + e * 32;                                                    \
        *(uint4*)(sm + OFF_KH + rr2 * 144 + psg * 16) = rh[e];                    \
        *(uint4*)(sm + OFF_KL + rr2 * 144 + psg * 16) = rl[e];                    \
    } } while (0)

    LDKV(KhB, KlB, 0);

    __syncthreads();
    uint32_t qhf[4][4], qlf[4][4];
#pragma unroll
    for (int ks = 0; ks < 4; ks++) {
        const uint32_t aro = (uint32_t)(wm * 16 + (lane & 15)) * 144 + ks * 32 + (lane >> 4) * 16;
        ldsm4(qhf[ks], sb + OFF_QH + aro);
        ldsm4(qlf[ks], sb + OFF_QL + aro);
    }

    // ---- Phase 1: QK^T + mask + exp + E (bf16 hi/lo) + row sums ----
    const float scale = 0.125f;
    const int frow = wm * 16 + (lane >> 2);
    float rs0 = 0.f, rs1 = 0.f;
    for (int c = 0; c < 16; c++) {
        STKV();
        __syncthreads();
        if (c < 15) LDKV(KhB, KlB, c + 1);
        else        LDKV(VhB, VlB, 0);

        float ahh[2][4], ahl[2][4], alh[2][4];
#pragma unroll
        for (int j = 0; j < 2; j++)
#pragma unroll
            for (int k = 0; k < 4; k++) { ahh[j][k] = 0.f; ahl[j][k] = 0.f; alh[j][k] = 0.f; }

#pragma unroll
        for (int ks = 0; ks < 4; ks++) {
            uint32_t kh4[4], kl4[4];
            const uint32_t bro = (uint32_t)(wn * 16 + (lane & 15)) * 144 + ks * 32 + (lane >> 4) * 16;
            ldsm4(kh4, sb + OFF_KH + bro);
            ldsm4(kl4, sb + OFF_KL + bro);
#pragma unroll
            for (int j = 0; j < 2; j++) {
                uint32_t bh2[2] = { kh4[j], kh4[2 + j] };
                uint32_t bl2[2] = { kl4[j], kl4[2 + j] };
                mma_bf16(ahh[j], qhf[ks], bh2);
                mma_bf16(ahl[j], qhf[ks], bl2);
                mma_bf16(alh[j], qlf[ks], bh2);
            }
        }
        const uint32_t word = (uint32_t)c * 2 + (wn >> 1);
        const uint32_t mw0 = *(const uint32_t*)(sm + OFF_MB + frow * 128 + word * 4);
        const uint32_t mw1 = *(const uint32_t*)(sm + OFF_MB + (frow + 8) * 128 + word * 4);
#pragma unroll
        for (int j = 0; j < 2; j++) {
            const int colb = (c * 64 + wn * 16 + j * 8 + 2 * (lane & 3)) * 2;
            const int bi = (wn & 1) * 16 + j * 8 + 2 * (lane & 3);
            float s0 = ahh[j][0] + (ahl[j][0] + alh[j][0]);
            float s1 = ahh[j][1] + (ahl[j][1] + alh[j][1]);
            float s2 = ahh[j][2] + (ahl[j][2] + alh[j][2]);
            float s3 = ahh[j][3] + (ahl[j][3] + alh[j][3]);
            float e0 = ((mw0 >> bi) & 1u)       ? 0.f : fast_exp(s0 * scale);
            float e1 = ((mw0 >> (bi + 1)) & 1u) ? 0.f : fast_exp(s1 * scale);
            float e2 = ((mw1 >> bi) & 1u)       ? 0.f : fast_exp(s2 * scale);
            float e3 = ((mw1 >> (bi + 1)) & 1u) ? 0.f : fast_exp(s3 * scale);
            rs0 += e0 + e1;
            rs1 += e2 + e3;
            __nv_bfloat162 h01, h23, l01, l23;
            h01.x = __float2bfloat16(e0); h01.y = __float2bfloat16(e1);
            h23.x = __float2bfloat16(e2); h23.y = __float2bfloat16(e3);
            l01.x = __float2bfloat16(e0 - __bfloat162float(h01.x));
            l01.y = __float2bfloat16(e1 - __bfloat162float(h01.y));
            l23.x = __float2bfloat16(e2 - __bfloat162float(h23.x));
            l23.y = __float2bfloat16(e3 - __bfloat162float(h23.y));
            *(uint32_t*)(sm + OFF_EH + frow * ESTRB + colb)       = *(uint32_t*)&h01;
            *(uint32_t*)(sm + OFF_EH + (frow + 8) * ESTRB + colb) = *(uint32_t*)&h23;
            *(uint32_t*)(sm + OFF_EL + frow * ESTRB + colb)       = *(uint32_t*)&l01;
            *(uint32_t*)(sm + OFF_EL + (frow + 8) * ESTRB + colb) = *(uint32_t*)&l23;
        }
        __syncthreads();
    }

    // ---- reduce row sums -> inv[32] ----
    rs0 += __shfl_xor_sync(0xffffffffu, rs0, 1);
    rs0 += __shfl_xor_sync(0xffffffffu, rs0, 2);
    rs1 += __shfl_xor_sync(0xffffffffu, rs1, 1);
    rs1 += __shfl_xor_sync(0xffffffffu, rs1, 2);
    if ((lane & 3) == 0) {
        float* sums = (float*)(sm + OFF_SUM);
        sums[frow * 4 + wn]       = rs0;
        sums[(frow + 8) * 4 + wn] = rs1;
    }
    __syncthreads();
    if (tid < 32) {
        const float* s4 = (const float*)(sm + OFF_SUM) + tid * 4;
        ((float*)(sm + OFF_INV))[tid] = 1.f / ((s4[0] + s4[1]) + (s4[2] + s4[3]));
    }
    __syncthreads();

    // ---- Phase 2: attnw = E * inv (normalize + stream) ----
#pragma unroll 1
    for (int rr = 0; rr < 4; rr++) {
        const int r = wid + rr * 8;
        const float inv = ((const float*)(sm + OFF_INV))[r];
        float4* arow4 = (float4*)(attnw + ((size_t)bh * Ss + q0 + r) * Ss);
#pragma unroll
        for (int i = 0; i < 8; i++) {
            const int cb = lane + i * 32;
            uint2 hh = *(uint2*)(sm + OFF_EH + (size_t)r * ESTRB + cb * 8);
            uint2 ll = *(uint2*)(sm + OFF_EL + (size_t)r * ESTRB + cb * 8);
            float2 h0 = __bfloat1622float2(*(__nv_bfloat162*)&hh.x);
            float2 h1 = __bfloat1622float2(*(__nv_bfloat162*)&hh.y);
            float2 l0 = __bfloat1622float2(*(__nv_bfloat162*)&ll.x);
            float2 l1 = __bfloat1622float2(*(__nv_bfloat162*)&ll.y);
            float4 p = make_float4((h0.x + l0.x) * inv, (h0.y + l0.y) * inv,
                                   (h1.x + l1.x) * inv, (h1.y + l1.y) * inv);
            __stcs(&arow4[cb], p);
        }
    }
    __syncthreads();

    // ---- Phase 3: AO = (E @ V) * inv ----
    float ahh[2][4], ahl[2][4], alh[2][4];
#pragma unroll
    for (int j = 0; j < 2; j++)
#pragma unroll
        for (int k = 0; k < 4; k++) { ahh[j][k] = 0.f; ahl[j][k] = 0.f; alh[j][k] = 0.f; }

    for (int c = 0; c < 16; c++) {
        STKV();
        __syncthreads();
        if (c < 15) LDKV(VhB, VlB, c + 1);

#pragma unroll
        for (int ks = 0; ks < 4; ks++) {
            uint32_t ph4[4], pl4[4], vh4[4], vl4[4];
            const uint32_t kbyte = (uint32_t)(c * 64 + ks * 16) * 2 + (lane >> 4) * 16;
            const uint32_t arow = (uint32_t)(wm * 16 + (lane & 15));
            ldsm4(ph4, sb + OFF_EH + arow * ESTRB + kbyte);
            ldsm4(pl4, sb + OFF_EL + arow * ESTRB + kbyte);
            const int g = lane >> 3;
            const uint32_t bro = (uint32_t)(ks * 16 + (g & 1) * 8 + (lane & 7)) * 144
                               + wn * 32 + (g >> 1) * 16;
            ldsm4t(vh4, sb + OFF_KH + bro);
            ldsm4t(vl4, sb + OFF_KL + bro);
#pragma unroll
            for (int j = 0; j < 2; j++) {
                uint32_t bh2[2] = { vh4[2 * j], vh4[2 * j + 1] };
                uint32_t bl2[2] = { vl4[2 * j], vl4[2 * j + 1] };
                mma_bf16(ahh[j], ph4, bh2);
                mma_bf16(ahl[j], ph4, bl2);
                mma_bf16(alh[j], pl4, bh2);
            }
        }
        __syncthreads();
    }

    // epilogue: AO * inv as bf16 hi/lo, row-major [B*S, D]
    {
        const float inv0 = ((const float*)(sm + OFF_INV))[frow];
        const float inv1 = ((const float*)(sm + OFF_INV))[frow + 8];
#pragma unroll
        for (int j = 0; j < 2; j++) {
            const int d = wn * 16 + j * 8 + 2 * (lane & 3);
#pragma unroll
            for (int hf = 0; hf < 2; hf++) {
                const int q = q0 + frow + hf * 8;
                const float iv = hf ? inv1 : inv0;
                float v0 = (ahh[j][hf * 2 + 0] + (ahl[j][hf * 2 + 0] + alh[j][hf * 2 + 0])) * iv;
                float v1 = (ahh[j][hf * 2 + 1] + (ahl[j][hf * 2 + 1] + alh[j][hf * 2 + 1])) * iv;
                __nv_bfloat16 h0 = __float2bfloat16(v0);
                __nv_bfloat16 h1 = __float2bfloat16(v1);
                __nv_bfloat162 hi2; hi2.x = h0; hi2.y = h1;
                __nv_bfloat162 lo2;
                lo2.x = __float2bfloat16(v0 - __bfloat162float(h0));
                lo2.y = __float2bfloat16(v1 - __bfloat162float(h1));
                const size_t idx = ((size_t)b * Ss + q) * Dd + h * DKk + d;
                *(__nv_bfloat162*)(g_Ah + idx) = hi2;
                *(__nv_bfloat162*)(g_Al + idx) = lo2;
            }
        }
    }
}

// ---------------------------------------------------------------------------
extern "C" void kernel_launch(void* const* d_in, const int* in_sizes, int n_in,
                              void* d_out, int out_size)
{
    const float* query = (const float*)d_in[0];
    const float* key_  = (const float*)d_in[1];
    const float* value = (const float*)d_in[2];
    const void*  mask  = d_in[3];
    const float* Wq = (const float*)d_in[4];
    const float* bq = (const float*)d_in[5];
    const float* Wk = (const float*)d_in[6];
    const float* bk = (const float*)d_in[7];
    const float* Wv = (const float*)d_in[8];
    const float* bv = (const float*)d_in[9];
    const float* Wo = (const float*)d_in[10];
    const float* bo = (const float*)d_in[11];

    float* out   = (float*)d_out;
    float* attnw = out + (size_t)Bb * Ss * Dd;

    __nv_bfloat16 *Ahp, *Alp, *Whp, *Wlp, *Qhp, *Qlp, *Khp, *Klp, *Vhp, *Vlp;
    cudaGetSymbolAddress((void**)&Ahp, g_Ah);
    cudaGetSymbolAddress((void**)&Alp, g_Al);
    cudaGetSymbolAddress((void**)&Whp, g_Wh);
    cudaGetSymbolAddress((void**)&Wlp, g_Wl);
    cudaGetSymbolAddress((void**)&Qhp, g_Qh);
    cudaGetSymbolAddress((void**)&Qlp, g_Ql);
    cudaGetSymbolAddress((void**)&Khp, g_Kh);
    cudaGetSymbolAddress((void**)&Klp, g_Kl);
    cudaGetSymbolAddress((void**)&Vhp, g_Vh);
    cudaGetSymbolAddress((void**)&Vlp, g_Vl);

    cudaFuncSetAttribute(gemm_qkv_kernel,
                         cudaFuncAttributeMaxDynamicSharedMemorySize, GEMM_SMEM3);
    cudaFuncSetAttribute(gemm_out_kernel,
                         cudaFuncAttributeMaxDynamicSharedMemorySize, GEMM_SMEM2);
    cudaFuncSetAttribute(attn_mma_kernel,
                         cudaFuncAttributeMaxDynamicSharedMemorySize, ATTN_SMEM);

    detect_mask_kernel<<<1, 256>>>((const unsigned char*)mask);
    pack_mask_kernel<<<Bb * Hh * Ss / 8, 256>>>(mask);

    // merged conversions
    conv_wT_kernel<<<dim3(Dd / 32, Dd / 32, 4), 256>>>(Wq, Wk, Wv, Wo, Whp, Wlp);
    conv_act_kernel<<<dim3(NROWS * Dd / 4 / 256, 3), 256>>>(query, key_, value, Ahp, Alp);

    // merged QKV projection (row-major outputs, 3-stage pipeline)
    gemm_qkv_kernel<<<dim3(Dd / 128, NROWS / 128, 3), 256, GEMM_SMEM3>>>(
        Ahp, Alp, Whp, Wlp, bq, bk, bv, Qhp, Qlp, Khp, Klp, Vhp, Vlp);

    // attention: writes attnw and AO hi/lo into act slot 0
    attn_mma_kernel<<<Bb * Hh * (Ss / 32), 256, ATTN_SMEM>>>(attnw);

    // out = AO @ Wo + bo
    gemm_out_kernel<<<dim3(Dd / 128, NROWS / 128), 256, GEMM_SMEM2>>>(
        Ahp, Alp, Whp + 3 * (size_t)Dd * Dd, Wlp + 3 * (size_t)Dd * Dd, bo, out);
}

// round 16
// speedup vs baseline: 1.0835x; 1.0835x over previous
#include <cuda_runtime.h>
#include <cuda_bf16.h>
#include <cstdint>
#include <math.h>

#define Bb   4
#define Ss   1024
#define Dd   1024
#define Hh   16
#define DKk  64
#define NROWS (Bb * Ss)       // 4096

// ---------------- scratch (device globals; allocation-free rule) -----------
__device__ __nv_bfloat16 g_Ah[3 * NROWS * Dd];  // act hi (z slots: q,k,v / AO in 0)
__device__ __nv_bfloat16 g_Al[3 * NROWS * Dd];
__device__ __nv_bfloat16 g_Wh[4 * Dd * Dd];     // W^T hi (q,k,v,o)
__device__ __nv_bfloat16 g_Wl[4 * Dd * Dd];
__device__ __nv_bfloat16 g_Qh[NROWS * Dd];      // row-major [B*S, D] (head at h*64)
__device__ __nv_bfloat16 g_Ql[NROWS * Dd];
__device__ __nv_bfloat16 g_Kh[NROWS * Dd];
__device__ __nv_bfloat16 g_Kl[NROWS * Dd];
__device__ __nv_bfloat16 g_Vh[NROWS * Dd];
__device__ __nv_bfloat16 g_Vl[NROWS * Dd];
__device__ uint32_t g_maskbits[(size_t)Bb * Hh * Ss * (Ss / 32)];   // 8 MB
__device__ int g_mask_is_byte;

// ---------------- PTX helpers ----------------------------------------------
__device__ __forceinline__ uint32_t smem_u32(const void* p) {
    uint32_t a;
    asm("{ .reg .u64 t; cvta.to.shared.u64 t, %1; cvt.u32.u64 %0, t; }"
        : "=r"(a) : "l"(p));
    return a;
}
__device__ __forceinline__ void ldsm4(uint32_t* r, uint32_t addr) {
    asm volatile("ldmatrix.sync.aligned.m8n8.x4.shared.b16 {%0,%1,%2,%3}, [%4];"
                 : "=r"(r[0]), "=r"(r[1]), "=r"(r[2]), "=r"(r[3]) : "r"(addr));
}
__device__ __forceinline__ void ldsm4t(uint32_t* r, uint32_t addr) {
    asm volatile("ldmatrix.sync.aligned.m8n8.x4.trans.shared.b16 {%0,%1,%2,%3}, [%4];"
                 : "=r"(r[0]), "=r"(r[1]), "=r"(r[2]), "=r"(r[3]) : "r"(addr));
}
__device__ __forceinline__ void mma_bf16(float* c, const uint32_t* a, const uint32_t* b) {
    asm volatile("mma.sync.aligned.m16n8k16.row.col.f32.bf16.bf16.f32 "
                 "{%0,%1,%2,%3}, {%4,%5,%6,%7}, {%8,%9}, {%0,%1,%2,%3};"
                 : "+f"(c[0]), "+f"(c[1]), "+f"(c[2]), "+f"(c[3])
                 : "r"(a[0]), "r"(a[1]), "r"(a[2]), "r"(a[3]), "r"(b[0]), "r"(b[1]));
}
#define CP_ASYNC16(dst, src) \
    asm volatile("cp.async.cg.shared.global [%0], [%1], 16;" :: "r"(dst), "l"(src))
#define CP_COMMIT() asm volatile("cp.async.commit_group;" ::: "memory")
#define CP_WAIT1()  asm volatile("cp.async.wait_group 1;" ::: "memory")
#define CP_WAIT0()  asm volatile("cp.async.wait_group 0;" ::: "memory")

// fast e^x. exp2 bit-trick + deg-5 poly (~1e-7 rel).
__device__ __forceinline__ float fast_exp(float x) {
    float t = x * 1.4426950408889634f;
    t = fmaxf(t, -126.0f);
    float fi = floorf(t);
    float f = t - fi;
    float p = 1.33336498402e-3f;
    p = fmaf(p, f, 9.81094791730e-3f);
    p = fmaf(p, f, 5.54906055839e-2f);
    p = fmaf(p, f, 2.40231509939e-1f);
    p = fmaf(p, f, 6.93146873954e-1f);
    p = fmaf(p, f, 1.0f);
    return __int_as_float(__float_as_int(p) + (((int)fi) << 23));
}

// ---------------------------------------------------------------------------
__global__ void detect_mask_kernel(const unsigned char* __restrict__ m)
{
    __shared__ int any;
    if (threadIdx.x == 0) any = 0;
    __syncthreads();
    int found = 0;
    for (int i = threadIdx.x; i < 4096; i += 256)
        if ((i & 3) != 0 && m[i] != 0) found = 1;
    if (found) atomicOr(&any, 1);
    __syncthreads();
    if (threadIdx.x == 0) g_mask_is_byte = any;
}

// pack mask -> bits. One warp per row of 1024.
__global__ __launch_bounds__(256)
void pack_mask_kernel(const void* __restrict__ mask_raw)
{
    const int row  = blockIdx.x * 8 + (threadIdx.x >> 5);
    const int lane = threadIdx.x & 31;
    uint32_t myw = 0;
    if (g_mask_is_byte) {
        const unsigned char* m = (const unsigned char*)mask_raw + (size_t)row * Ss;
#pragma unroll 4
        for (int it = 0; it < 32; it++) {
            uint32_t w = __ballot_sync(0xffffffffu, m[it * 32 + lane] != 0);
            if (it == lane) myw = w;
        }
    } else {
        const int* m = (const int*)mask_raw + (size_t)row * Ss;
#pragma unroll 4
        for (int it = 0; it < 32; it++) {
            uint32_t w = __ballot_sync(0xffffffffu, m[it * 32 + lane] != 0);
            if (it == lane) myw = w;
        }
    }
    g_maskbits[(size_t)row * 32 + lane] = myw;
}

// ---------------------------------------------------------------------------
// merged act conversion: z = 0,1,2 selects query/key/value
__global__ __launch_bounds__(256)
void conv_act_kernel(const float* __restrict__ A0, const float* __restrict__ A1,
                     const float* __restrict__ A2,
                     __nv_bfloat16* __restrict__ hiB, __nv_bfloat16* __restrict__ loB)
{
    const int z = blockIdx.y;
    const float* A = (z == 0) ? A0 : (z == 1) ? A1 : A2;
    __nv_bfloat16* hi = hiB + (size_t)z * NROWS * Dd;
    __nv_bfloat16* lo = loB + (size_t)z * NROWS * Dd;
    int i = blockIdx.x * 256 + threadIdx.x;
    float4 v = ((const float4*)A)[i];
    __nv_bfloat16 h0 = __float2bfloat16(v.x);
    __nv_bfloat16 h1 = __float2bfloat16(v.y);
    __nv_bfloat16 h2 = __float2bfloat16(v.z);
    __nv_bfloat16 h3 = __float2bfloat16(v.w);
    __nv_bfloat162 hA; hA.x = h0; hA.y = h1;
    __nv_bfloat162 hB; hB.x = h2; hB.y = h3;
    __nv_bfloat162 lA, lB;
    lA.x = __float2bfloat16(v.x - __bfloat162float(h0));
    lA.y = __float2bfloat16(v.y - __bfloat162float(h1));
    lB.x = __float2bfloat16(v.z - __bfloat162float(h2));
    lB.y = __float2bfloat16(v.w - __bfloat162float(h3));
    ((__nv_bfloat162*)hi)[i * 2 + 0] = hA;
    ((__nv_bfloat162*)hi)[i * 2 + 1] = hB;
    ((__nv_bfloat162*)lo)[i * 2 + 0] = lA;
    ((__nv_bfloat162*)lo)[i * 2 + 1] = lB;
}

// merged weight transpose+split: z = 0..3 selects Wq/Wk/Wv/Wo
__global__ __launch_bounds__(256)
void conv_wT_kernel(const float* __restrict__ W0, const float* __restrict__ W1,
                    const float* __restrict__ W2, const float* __restrict__ W3,
                    __nv_bfloat16* __restrict__ WhB, __nv_bfloat16* __restrict__ WlB)
{
    __shared__ float t[32][33];
    const int z = blockIdx.z;
    const float* W = (z == 0) ? W0 : (z == 1) ? W1 : (z == 2) ? W2 : W3;
    __nv_bfloat16* WhT = WhB + (size_t)z * Dd * Dd;
    __nv_bfloat16* WlT = WlB + (size_t)z * Dd * Dd;
    const int n0 = blockIdx.x * 32, k0 = blockIdx.y * 32;
    const int tx = threadIdx.x & 31, ty = threadIdx.x >> 5;
    for (int r = ty; r < 32; r += 8)
        t[r][tx] = W[(size_t)(k0 + r) * Dd + n0 + tx];
    __syncthreads();
    for (int r = ty; r < 32; r += 8) {
        float x = t[tx][r];
        __nv_bfloat16 h = __float2bfloat16(x);
        __nv_bfloat16 l = __float2bfloat16(x - __bfloat162float(h));
        WhT[(size_t)(n0 + r) * Dd + k0 + tx] = h;
        WlT[(size_t)(n0 + r) * Dd + k0 + tx] = l;
    }
}

// ---------------------------------------------------------------------------
// GEMM mainloop body shared by both gemm kernels (R14 2-stage form)
// ---------------------------------------------------------------------------
#define KCH   32
#define NCHNK (Dd / KCH)
#define RSTB  80
#define TILEB (128 * RSTB)
#define STAGEB (4 * TILEB)
#define GEMM_SMEM (2 * STAGEB)

#define GEMM_MAINLOOP(Ah, Al, Bh, Bl)                                          \
    float acc[2][8][4];                                                        \
    _Pragma("unroll")                                                          \
    for (int mt = 0; mt < 2; mt++)                                             \
        _Pragma("unroll")                                                      \
        for (int nt = 0; nt < 8; nt++)                                         \
            _Pragma("unroll")                                                  \
            for (int j = 0; j < 4; j++) acc[mt][nt][j] = 0.f;                  \
    auto load_stage = [&](int stg, int kc) {                                   \
        const uint32_t base = sb + stg * STAGEB;                               \
        _Pragma("unroll")                                                      \
        for (int e = 0; e < 2; e++) {                                          \
            const int row = r0 + e * 64;                                       \
            const uint32_t so = (uint32_t)row * RSTB + sg * 16;                \
            const size_t gaoff = (size_t)(m0 + row) * Dd + kc + sg * 8;        \
            const size_t gboff = (size_t)(n0 + row) * Dd + kc + sg * 8;        \
            CP_ASYNC16(base + 0 * TILEB + so, (const char*)(Ah + gaoff));      \
            CP_ASYNC16(base + 1 * TILEB + so, (const char*)(Al + gaoff));      \
            CP_ASYNC16(base + 2 * TILEB + so, (const char*)(Bh + gboff));      \
            CP_ASYNC16(base + 3 * TILEB + so, (const char*)(Bl + gboff));      \
        }                                                                      \
    };                                                                         \
    load_stage(0, 0);                                                          \
    CP_COMMIT();                                                               \
    for (int ch = 0; ch < NCHNK; ch++) {                                       \
        if (ch + 1 < NCHNK) {                                                  \
            load_stage((ch + 1) & 1, (ch + 1) * KCH);                          \
            CP_COMMIT();                                                       \
            CP_WAIT1();                                                        \
        } else {                                                               \
            CP_WAIT0();                                                        \
        }                                                                      \
        __syncthreads();                                                       \
        const uint32_t bA = sb + (ch & 1) * STAGEB;                            \
        _Pragma("unroll")                                                      \
        for (int ks = 0; ks < 2; ks++) {                                       \
            const uint32_t koff = ks * 32 + (lane >> 4) * 16;                  \
            uint32_t ahf[2][4], alf[2][4], bhf[4][4], blf[4][4];               \
            _Pragma("unroll")                                                  \
            for (int mt = 0; mt < 2; mt++) {                                   \
                const uint32_t ro = (uint32_t)(wm * 32 + mt * 16 + (lane & 15)) * RSTB + koff; \
                ldsm4(ahf[mt], bA + 0 * TILEB + ro);                           \
                ldsm4(alf[mt], bA + 1 * TILEB + ro);                           \
            }                                                                  \
            _Pragma("unroll")                                                  \
            for (int np = 0; np < 4; np++) {                                   \
                const uint32_t ro = (uint32_t)(wn * 64 + np * 16 + (lane & 15)) * RSTB + koff; \
                ldsm4(bhf[np], bA + 2 * TILEB + ro);                           \
                ldsm4(blf[np], bA + 3 * TILEB + ro);                           \
            }                                                                  \
            _Pragma("unroll")                                                  \
            for (int mt = 0; mt < 2; mt++)                                     \
                _Pragma("unroll")                                              \
                for (int nt = 0; nt < 8; nt++) {                               \
                    uint32_t bh2[2] = { bhf[nt >> 1][nt & 1], bhf[nt >> 1][2 + (nt & 1)] }; \
                    uint32_t bl2[2] = { blf[nt >> 1][nt & 1], blf[nt >> 1][2 + (nt & 1)] }; \
                    mma_bf16(acc[mt][nt], ahf[mt], bh2);                       \
                    mma_bf16(acc[mt][nt], ahf[mt], bl2);                       \
                    mma_bf16(acc[mt][nt], alf[mt], bh2);                       \
                }                                                              \
        }                                                                      \
        __syncthreads();                                                       \
    }

// merged QKV projection GEMM (row-major bf16 hi/lo epilogue; natural regs)
__global__ __launch_bounds__(256)
void gemm_qkv_kernel(const __nv_bfloat16* __restrict__ AhB, const __nv_bfloat16* __restrict__ AlB,
                     const __nv_bfloat16* __restrict__ WhB, const __nv_bfloat16* __restrict__ WlB,
                     const float* __restrict__ b0, const float* __restrict__ b1,
                     const float* __restrict__ b2,
                     __nv_bfloat16* __restrict__ Qh, __nv_bfloat16* __restrict__ Ql,
                     __nv_bfloat16* __restrict__ Kh, __nv_bfloat16* __restrict__ Kl,
                     __nv_bfloat16* __restrict__ Vh, __nv_bfloat16* __restrict__ Vl)
{
    extern __shared__ char smem[];
    const uint32_t sb = smem_u32(smem);
    const int tid  = threadIdx.x;
    const int lane = tid & 31, wid = tid >> 5;
    const int wm = wid & 3, wn = wid >> 2;
    const int m0 = blockIdx.y * 128;
    const int n0 = blockIdx.x * 128;
    const int r0 = tid >> 2, sg = tid & 3;
    const int z  = blockIdx.z;

    const __nv_bfloat16* Ah = AhB + (size_t)z * NROWS * Dd;
    const __nv_bfloat16* Al = AlB + (size_t)z * NROWS * Dd;
    const __nv_bfloat16* Bh = WhB + (size_t)z * Dd * Dd;
    const __nv_bfloat16* Bl = WlB + (size_t)z * Dd * Dd;
    const float* bias = (z == 0) ? b0 : (z == 1) ? b1 : b2;
    __nv_bfloat16* Ch = (z == 0) ? Qh : (z == 1) ? Kh : Vh;
    __nv_bfloat16* Cl = (z == 0) ? Ql : (z == 1) ? Kl : Vl;

    GEMM_MAINLOOP(Ah, Al, Bh, Bl)

#pragma unroll
    for (int mt = 0; mt < 2; mt++) {
        const int r = m0 + wm * 32 + mt * 16 + (lane >> 2);
#pragma unroll
        for (int nt = 0; nt < 8; nt++) {
            const int c = n0 + wn * 64 + nt * 8 + 2 * (lane & 3);
            const float bb0 = bias[c], bb1 = bias[c + 1];
#pragma unroll
            for (int hf = 0; hf < 2; hf++) {
                const int rr = r + hf * 8;
                float v0 = acc[mt][nt][hf * 2 + 0] + bb0;
                float v1 = acc[mt][nt][hf * 2 + 1] + bb1;
                __nv_bfloat16 h0 = __float2bfloat16(v0);
                __nv_bfloat16 h1 = __float2bfloat16(v1);
                __nv_bfloat162 hi2; hi2.x = h0; hi2.y = h1;
                __nv_bfloat162 lo2;
                lo2.x = __float2bfloat16(v0 - __bfloat162float(h0));
                lo2.y = __float2bfloat16(v1 - __bfloat162float(h1));
                const size_t idx = (size_t)rr * Dd + c;
                *(__nv_bfloat162*)(Ch + idx) = hi2;
                *(__nv_bfloat162*)(Cl + idx) = lo2;
            }
        }
    }
}

// final output GEMM: fp32 row-major epilogue (fits 128 regs -> 2 CTAs/SM)
__global__ __launch_bounds__(256, 2)
void gemm_out_kernel(const __nv_bfloat16* __restrict__ Ah, const __nv_bfloat16* __restrict__ Al,
                     const __nv_bfloat16* __restrict__ Bh, const __nv_bfloat16* __restrict__ Bl,
                     const float* __restrict__ bias, float* __restrict__ Cf)
{
    extern __shared__ char smem[];
    const uint32_t sb = smem_u32(smem);
    const int tid  = threadIdx.x;
    const int lane = tid & 31, wid = tid >> 5;
    const int wm = wid & 3, wn = wid >> 2;
    const int m0 = blockIdx.y * 128;
    const int n0 = blockIdx.x * 128;
    const int r0 = tid >> 2, sg = tid & 3;

    GEMM_MAINLOOP(Ah, Al, Bh, Bl)

#pragma unroll
    for (int mt = 0; mt < 2; mt++) {
        const int r = m0 + wm * 32 + mt * 16 + (lane >> 2);
#pragma unroll
        for (int nt = 0; nt < 8; nt++) {
            const int c = n0 + wn * 64 + nt * 8 + 2 * (lane & 3);
            const float bb0 = bias[c], bb1 = bias[c + 1];
            float2 v0 = make_float2(acc[mt][nt][0] + bb0, acc[mt][nt][1] + bb1);
            float2 v1 = make_float2(acc[mt][nt][2] + bb0, acc[mt][nt][3] + bb1);
            *(float2*)&Cf[(size_t)r * Dd + c]       = v0;
            *(float2*)&Cf[(size_t)(r + 8) * Dd + c] = v1;
        }
    }
}

// ---------------------------------------------------------------------------
// Attention v4: R14 + double-buffered K/V chunk smem (1 barrier per chunk).
// ---------------------------------------------------------------------------
#define ESTRB  2096
#define OFF_EH 0
#define OFF_EL 67072
#define OFF_QH 134144              // 4608
#define OFF_QL 138752              // 4608 -> 143360
#define OFF_KV 143360              // 2 stages x (KH 9216 + KL 9216) -> 180224
#define KVSTG  18432
#define OFF_MB 180224              // 4096 -> 184320
#define OFF_SUM 184320             // 512  -> 184832
#define OFF_INV 184832             // 128  -> 184960
#define ATTN_SMEM 184960

__global__ __launch_bounds__(256)
void attn_mma_kernel(float* __restrict__ attnw)
{
    extern __shared__ char sm[];
    const uint32_t sb = smem_u32(sm);

    const int blk = blockIdx.x;
    const int qt  = blk & 31;
    const int bh  = blk >> 5;
    const int q0  = qt * 32;
    const int tid = threadIdx.x;
    const int lane = tid & 31, wid = tid >> 5;
    const int wm = wid & 1;
    const int wn = wid >> 1;
    const int b  = bh >> 4, h = bh & 15;

    const __nv_bfloat16* QhB = g_Qh + ((size_t)b * Ss + q0) * Dd + h * DKk;
    const __nv_bfloat16* QlB = g_Ql + ((size_t)b * Ss + q0) * Dd + h * DKk;
    const __nv_bfloat16* KhB = g_Kh + (size_t)b * Ss * Dd + h * DKk;
    const __nv_bfloat16* KlB = g_Kl + (size_t)b * Ss * Dd + h * DKk;
    const __nv_bfloat16* VhB = g_Vh + (size_t)b * Ss * Dd + h * DKk;
    const __nv_bfloat16* VlB = g_Vl + (size_t)b * Ss * Dd + h * DKk;

    {
        int r = tid >> 3, sg = tid & 7;
        *(uint4*)(sm + OFF_QH + r * 144 + sg * 16) = ((const uint4*)(QhB + (size_t)r * Dd))[sg];
        *(uint4*)(sm + OFF_QL + r * 144 + sg * 16) = ((const uint4*)(QlB + (size_t)r * Dd))[sg];
        const uint4* msrc = (const uint4*)(g_maskbits + ((size_t)bh * Ss + q0 + r) * 32) + sg;
        *(uint4*)(sm + OFF_MB + r * 128 + sg * 16) = *msrc;
    }

    const int pr = tid >> 3, psg = tid & 7;
    uint4 rh[2], rl[2];
#define LDKV(Hb, Lb, c) do {                                                      \
    _Pragma("unroll")                                                             \
    for (int e = 0; e < 2; e++) {                                                 \
        int rr2 = pr + e * 32;                                                    \
        rh[e] = ((const uint4*)((Hb) + (size_t)((c) * 64 + rr2) * Dd))[psg];      \
        rl[e] = ((const uint4*)((Lb) + (size_t)((c) * 64 + rr2) * Dd))[psg];      \
    } } while (0)
#define STKV(s) do {                                                              \
    const uint32_t kb = OFF_KV + (uint32_t)(s) * KVSTG;                           \
    _Pragma("unroll")                                                             \
    for (int e = 0; e < 2; e++) {                                                 \
        int rr2 = pr + e * 32;                                                    \
        *(uint4*)(sm + kb + rr2 * 144 + psg * 16)        = rh[e];                 \
        *(uint4*)(sm + kb + 9216 + rr2 * 144 + psg * 16) = rl[e];                 \
    } } while (0)

    // prologue: chunk0 -> buf0, chunk1 in regs
    LDKV(KhB, KlB, 0);
    STKV(0);
    __syncthreads();
    uint32_t qhf[4][4], qlf[4][4];
#pragma unroll
    for (int ks = 0; ks < 4; ks++) {
        const uint32_t aro = (uint32_t)(wm * 16 + (lane & 15)) * 144 + ks * 32 + (lane >> 4) * 16;
        ldsm4(qhf[ks], sb + OFF_QH + aro);
        ldsm4(qlf[ks], sb + OFF_QL + aro);
    }
    LDKV(KhB, KlB, 1);

    // ---- Phase 1: QK^T + mask + exp + E (bf16 hi/lo) + row sums ----
    const float scale = 0.125f;
    const int frow = wm * 16 + (lane >> 2);
    float rs0 = 0.f, rs1 = 0.f;
    for (int c = 0; c < 16; c++) {
        // store chunk c+1 into other buffer (c=15: V chunk 0 -> buf 0)
        STKV((c + 1) & 1);
        // load chunk c+2 (K for <16, V for >=16)
        if (c + 2 < 16)       LDKV(KhB, KlB, c + 2);
        else if (c + 2 < 18)  LDKV(VhB, VlB, c + 2 - 16);

        float ahh[2][4], ahl[2][4], alh[2][4];
#pragma unroll
        for (int j = 0; j < 2; j++)
#pragma unroll
            for (int k = 0; k < 4; k++) { ahh[j][k] = 0.f; ahl[j][k] = 0.f; alh[j][k] = 0.f; }

        const uint32_t kvb = sb + OFF_KV + (uint32_t)(c & 1) * KVSTG;
#pragma unroll
        for (int ks = 0; ks < 4; ks++) {
            uint32_t kh4[4], kl4[4];
            const uint32_t bro = (uint32_t)(wn * 16 + (lane & 15)) * 144 + ks * 32 + (lane >> 4) * 16;
            ldsm4(kh4, kvb + bro);
            ldsm4(kl4, kvb + 9216 + bro);
#pragma unroll
            for (int j = 0; j < 2; j++) {
                uint32_t bh2[2] = { kh4[j], kh4[2 + j] };
                uint32_t bl2[2] = { kl4[j], kl4[2 + j] };
                mma_bf16(ahh[j], qhf[ks], bh2);
                mma_bf16(ahl[j], qhf[ks], bl2);
                mma_bf16(alh[j], qlf[ks], bh2);
            }
        }
        const uint32_t word = (uint32_t)c * 2 + (wn >> 1);
        const uint32_t mw0 = *(const uint32_t*)(sm + OFF_MB + frow * 128 + word * 4);
        const uint32_t mw1 = *(const uint32_t*)(sm + OFF_MB + (frow + 8) * 128 + word * 4);
#pragma unroll
        for (int j = 0; j < 2; j++) {
            const int colb = (c * 64 + wn * 16 + j * 8 + 2 * (lane & 3)) * 2;
            const int bi = (wn & 1) * 16 + j * 8 + 2 * (lane & 3);
            float s0 = ahh[j][0] + (ahl[j][0] + alh[j][0]);
            float s1 = ahh[j][1] + (ahl[j][1] + alh[j][1]);
            float s2 = ahh[j][2] + (ahl[j][2] + alh[j][2]);
            float s3 = ahh[j][3] + (ahl[j][3] + alh[j][3]);
            float e0 = ((mw0 >> bi) & 1u)       ? 0.f : fast_exp(s0 * scale);
            float e1 = ((mw0 >> (bi + 1)) & 1u) ? 0.f : fast_exp(s1 * scale);
            float e2 = ((mw1 >> bi) & 1u)       ? 0.f : fast_exp(s2 * scale);
            float e3 = ((mw1 >> (bi + 1)) & 1u) ? 0.f : fast_exp(s3 * scale);
            rs0 += e0 + e1;
            rs1 += e2 + e3;
            __nv_bfloat162 h01, h23, l01, l23;
            h01.x = __float2bfloat16(e0); h01.y = __float2bfloat16(e1);
            h23.x = __float2bfloat16(e2); h23.y = __float2bfloat16(e3);
            l01.x = __float2bfloat16(e0 - __bfloat162float(h01.x));
            l01.y = __float2bfloat16(e1 - __bfloat162float(h01.y));
            l23.x = __float2bfloat16(e2 - __bfloat162float(h23.x));
            l23.y = __float2bfloat16(e3 - __bfloat162float(h23.y));
            *(uint32_t*)(sm + OFF_EH + frow * ESTRB + colb)       = *(uint32_t*)&h01;
            *(uint32_t*)(sm + OFF_EH + (frow + 8) * ESTRB + colb) = *(uint32_t*)&h23;
            *(uint32_t*)(sm + OFF_EL + frow * ESTRB + colb)       = *(uint32_t*)&l01;
            *(uint32_t*)(sm + OFF_EL + (frow + 8) * ESTRB + colb) = *(uint32_t*)&l23;
        }
        __syncthreads();
    }

    // ---- reduce row sums -> inv[32] ----
    rs0 += __shfl_xor_sync(0xffffffffu, rs0, 1);
    rs0 += __shfl_xor_sync(0xffffffffu, rs0, 2);
    rs1 += __shfl_xor_sync(0xffffffffu, rs1, 1);
    rs1 += __shfl_xor_sync(0xffffffffu, rs1, 2);
    if ((lane & 3) == 0) {
        float* sums = (float*)(sm + OFF_SUM);
        sums[frow * 4 + wn]       = rs0;
        sums[(frow + 8) * 4 + wn] = rs1;
    }
    __syncthreads();
    if (tid < 32) {
        const float* s4 = (const float*)(sm + OFF_SUM) + tid * 4;
        ((float*)(sm + OFF_INV))[tid] = 1.f / ((s4[0] + s4[1]) + (s4[2] + s4[3]));
    }
    __syncthreads();

    // ---- Phase 2: attnw = E * inv (normalize + stream) ----
#pragma unroll 1
    for (int rr = 0; rr < 4; rr++) {
        const int r = wid + rr * 8;
        const float inv = ((const float*)(sm + OFF_INV))[r];
        float4* arow4 = (float4*)(attnw + ((size_t)bh * Ss + q0 + r) * Ss);
#pragma unroll
        for (int i = 0; i < 8; i++) {
            const int cb = lane + i * 32;
            uint2 hh = *(uint2*)(sm + OFF_EH + (size_t)r * ESTRB + cb * 8);
            uint2 ll = *(uint2*)(sm + OFF_EL + (size_t)r * ESTRB + cb * 8);
            float2 h0 = __bfloat1622float2(*(__nv_bfloat162*)&hh.x);
            float2 h1 = __bfloat1622float2(*(__nv_bfloat162*)&hh.y);
            float2 l0 = __bfloat1622float2(*(__nv_bfloat162*)&ll.x);
            float2 l1 = __bfloat1622float2(*(__nv_bfloat162*)&ll.y);
            float4 p = make_float4((h0.x + l0.x) * inv, (h0.y + l0.y) * inv,
                                   (h1.x + l1.x) * inv, (h1.y + l1.y) * inv);
            __stcs(&arow4[cb], p);
        }
    }
    __syncthreads();

    // ---- Phase 3: AO = (E @ V) * inv ----
    // V chunk 0 already in buf0 (stored at phase-1 c=15); V chunk 1 in regs.
    float ahh[2][4], ahl[2][4], alh[2][4];
#pragma unroll
    for (int j = 0; j < 2; j++)
#pragma unroll
        for (int k = 0; k < 4; k++) { ahh[j][k] = 0.f; ahl[j][k] = 0.f; alh[j][k] = 0.f; }

    for (int c = 0; c < 16; c++) {
        if (c < 15) STKV((c + 1) & 1);          // store V chunk c+1 regs
        if (c + 2 < 16) LDKV(VhB, VlB, c + 2);  // load V chunk c+2

        const uint32_t kvb = sb + OFF_KV + (uint32_t)(c & 1) * KVSTG;
#pragma unroll
        for (int ks = 0; ks < 4; ks++) {
            uint32_t ph4[4], pl4[4], vh4[4], vl4[4];
            const uint32_t kbyte = (uint32_t)(c * 64 + ks * 16) * 2 + (lane >> 4) * 16;
            const uint32_t arow = (uint32_t)(wm * 16 + (lane & 15));
            ldsm4(ph4, sb + OFF_EH + arow * ESTRB + kbyte);
            ldsm4(pl4, sb + OFF_EL + arow * ESTRB + kbyte);
            const int g = lane >> 3;
            const uint32_t bro = (uint32_t)(ks * 16 + (g & 1) * 8 + (lane & 7)) * 144
                               + wn * 32 + (g >> 1) * 16;
            ldsm4t(vh4, kvb + bro);
            ldsm4t(vl4, kvb + 9216 + bro);
#pragma unroll
            for (int j = 0; j < 2; j++) {
                uint32_t bh2[2] = { vh4[2 * j], vh4[2 * j + 1] };
                uint32_t bl2[2] = { vl4[2 * j], vl4[2 * j + 1] };
                mma_bf16(ahh[j], ph4, bh2);
                mma_bf16(ahl[j], ph4, bl2);
                mma_bf16(alh[j], pl4, bh2);
            }
        }
        __syncthreads();
    }

    // epilogue: AO * inv as bf16 hi/lo, row-major [B*S, D]
    {
        const float inv0 = ((const float*)(sm + OFF_INV))[frow];
        const float inv1 = ((const float*)(sm + OFF_INV))[frow + 8];
#pragma unroll
        for (int j = 0; j < 2; j++) {
            const int d = wn * 16 + j * 8 + 2 * (lane & 3);
#pragma unroll
            for (int hf = 0; hf < 2; hf++) {
                const int q = q0 + frow + hf * 8;
                const float iv = hf ? inv1 : inv0;
                float v0 = (ahh[j][hf * 2 + 0] + (ahl[j][hf * 2 + 0] + alh[j][hf * 2 + 0])) * iv;
                float v1 = (ahh[j][hf * 2 + 1] + (ahl[j][hf * 2 + 1] + alh[j][hf * 2 + 1])) * iv;
                __nv_bfloat16 h0 = __float2bfloat16(v0);
                __nv_bfloat16 h1 = __float2bfloat16(v1);
                __nv_bfloat162 hi2; hi2.x = h0; hi2.y = h1;
                __nv_bfloat162 lo2;
                lo2.x = __float2bfloat16(v0 - __bfloat162float(h0));
                lo2.y = __float2bfloat16(v1 - __bfloat162float(h1));
                const size_t idx = ((size_t)b * Ss + q) * Dd + h * DKk + d;
                *(__nv_bfloat162*)(g_Ah + idx) = hi2;
                *(__nv_bfloat162*)(g_Al + idx) = lo2;
            }
        }
    }
}

// ---------------------------------------------------------------------------
extern "C" void kernel_launch(void* const* d_in, const int* in_sizes, int n_in,
                              void* d_out, int out_size)
{
    const float* query = (const float*)d_in[0];
    const float* key_  = (const float*)d_in[1];
    const float* value = (const float*)d_in[2];
    const void*  mask  = d_in[3];
    const float* Wq = (const float*)d_in[4];
    const float* bq = (const float*)d_in[5];
    const float* Wk = (const float*)d_in[6];
    const float* bk = (const float*)d_in[7];
    const float* Wv = (const float*)d_in[8];
    const float* bv = (const float*)d_in[9];
    const float* Wo = (const float*)d_in[10];
    const float* bo = (const float*)d_in[11];

    float* out   = (float*)d_out;
    float* attnw = out + (size_t)Bb * Ss * Dd;

    __nv_bfloat16 *Ahp, *Alp, *Whp, *Wlp, *Qhp, *Qlp, *Khp, *Klp, *Vhp, *Vlp;
    cudaGetSymbolAddress((void**)&Ahp, g_Ah);
    cudaGetSymbolAddress((void**)&Alp, g_Al);
    cudaGetSymbolAddress((void**)&Whp, g_Wh);
    cudaGetSymbolAddress((void**)&Wlp, g_Wl);
    cudaGetSymbolAddress((void**)&Qhp, g_Qh);
    cudaGetSymbolAddress((void**)&Qlp, g_Ql);
    cudaGetSymbolAddress((void**)&Khp, g_Kh);
    cudaGetSymbolAddress((void**)&Klp, g_Kl);
    cudaGetSymbolAddress((void**)&Vhp, g_Vh);
    cudaGetSymbolAddress((void**)&Vlp, g_Vl);

    cudaFuncSetAttribute(gemm_qkv_kernel,
                         cudaFuncAttributeMaxDynamicSharedMemorySize, GEMM_SMEM);
    cudaFuncSetAttribute(gemm_out_kernel,
                         cudaFuncAttributeMaxDynamicSharedMemorySize, GEMM_SMEM);
    cudaFuncSetAttribute(attn_mma_kernel,
                         cudaFuncAttributeMaxDynamicSharedMemorySize, ATTN_SMEM);

    detect_mask_kernel<<<1, 256>>>((const unsigned char*)mask);
    pack_mask_kernel<<<Bb * Hh * Ss / 8, 256>>>(mask);

    // merged conversions
    conv_wT_kernel<<<dim3(Dd / 32, Dd / 32, 4), 256>>>(Wq, Wk, Wv, Wo, Whp, Wlp);
    conv_act_kernel<<<dim3(NROWS * Dd / 4 / 256, 3), 256>>>(query, key_, value, Ahp, Alp);

    // merged QKV projection (row-major outputs)
    gemm_qkv_kernel<<<dim3(Dd / 128, NROWS / 128, 3), 256, GEMM_SMEM>>>(
        Ahp, Alp, Whp, Wlp, bq, bk, bv, Qhp, Qlp, Khp, Klp, Vhp, Vlp);

    // attention: writes attnw and AO hi/lo into act slot 0
    attn_mma_kernel<<<Bb * Hh * (Ss / 32), 256, ATTN_SMEM>>>(attnw);

    // out = AO @ Wo + bo
    gemm_out_kernel<<<dim3(Dd / 128, NROWS / 128), 256, GEMM_SMEM>>>(
        Ahp, Alp, Whp + 3 * (size_t)Dd * Dd, Wlp + 3 * (size_t)Dd * Dd, bo, out);
}